// round 15
// baseline (speedup 1.0000x reference)
#include <cuda_runtime.h>
#include <cstddef>

// Pixel_RNNcontrol: h_t = tanh(x_t @ W_ih^T + h_{t-1} @ W_hh^T + b), out = sigmoid(10 h_t)
// T=128, B=262144, I=H=2.
//
// R15: 256-bit global accesses (ld/st.global.v8.f32, sm_100+). One thread now
// handles 4 batch elements (32B/step). Width series so far: float2 61.6% DRAM,
// float4 75.3% -> widest access wins on this mixed stream; request count to
// L2/DRAM halves at double payload. Loads .cg (R14 win), stores .cs (R12).
// PF=3 register pipeline, R10 loop structure. Fallback float4 kernel for
// npairs odd.

#define PF  3
#define TPB 256

struct F8 { float v[8]; };

__device__ __forceinline__ F8 ld256cg(const float* p) {
    F8 r;
    asm("ld.global.cg.v8.f32 {%0,%1,%2,%3,%4,%5,%6,%7}, [%8];"
        : "=f"(r.v[0]), "=f"(r.v[1]), "=f"(r.v[2]), "=f"(r.v[3]),
          "=f"(r.v[4]), "=f"(r.v[5]), "=f"(r.v[6]), "=f"(r.v[7])
        : "l"(p));
    return r;
}

__device__ __forceinline__ void st256cs(float* p, const F8& r) {
    asm volatile("st.global.cs.v8.f32 [%0], {%1,%2,%3,%4,%5,%6,%7,%8};"
        :: "l"(p),
           "f"(r.v[0]), "f"(r.v[1]), "f"(r.v[2]), "f"(r.v[3]),
           "f"(r.v[4]), "f"(r.v[5]), "f"(r.v[6]), "f"(r.v[7])
        : "memory");
}

__device__ __forceinline__ float exact_tanh(float z) {
    // tanh(z) = 1 - 2/(1 + e^{2z}); z bounded (|z| <~ 7) -> no overflow
    float k = 2.885390082f * z;        // 2*log2(e) * z
    float e;
    asm("ex2.approx.f32 %0, %1;" : "=f"(e) : "f"(k));
    float r;
    float d = e + 1.0f;
    asm("rcp.approx.f32 %0, %1;" : "=f"(r) : "f"(d));
    return fmaf(-2.0f, r, 1.0f);
}

__device__ __forceinline__ float sig10(float h) {
    // sigmoid(10h) = 0.5 + 0.5*tanh(5h); HW tanh -> 1 MUFU, error non-accumulating
    float t;
    float a = 5.0f * h;
    asm("tanh.approx.f32 %0, %1;" : "=f"(t) : "f"(a));
    return fmaf(0.5f, t, 0.5f);
}

__global__ void __launch_bounds__(TPB, 2)
rnn_wide_kernel(const float* __restrict__ x,
                const float* __restrict__ h0g,
                const float* __restrict__ Wih,
                const float* __restrict__ Whh,
                const float* __restrict__ bih,
                const float* __restrict__ bhh,
                float* __restrict__ out,
                float* __restrict__ houtg,
                int T, int nq)            // nq = B/4 (quads of batch elements)
{
    int q = blockIdx.x * TPB + threadIdx.x;
    if (q >= nq) return;

    const float a00 = Wih[0], a01 = Wih[1], a10 = Wih[2], a11 = Wih[3];
    const float w00 = Whh[0], w01 = Whh[1], w10 = Whh[2], w11 = Whh[3];
    const float b0 = bih[0] + bhh[0];
    const float b1 = bih[1] + bhh[1];

    const size_t strideF = (size_t)nq * 8;       // floats per timestep
    const float* xq = x + (size_t)q * 8;

    F8 h = ld256cg(h0g + (size_t)q * 8);          // 4 elems x 2 channels

    // Prime the pipeline.
    F8 buf[PF];
    #pragma unroll
    for (int i = 0; i < PF; ++i) {
        int ti = (i < T) ? i : (T - 1);
        buf[i] = ld256cg(xq + (size_t)ti * strideF);
    }

    const float* xld = xq + (size_t)PF * strideF;
    float*       ost = out + (size_t)q * 8;

    int t = 0;

    // Main loop: all PF prefetch loads in-range.
    for (; t + 2 * PF <= T; t += PF) {
        #pragma unroll
        for (int i = 0; i < PF; ++i) {
            F8 xv = buf[i];
            buf[i] = ld256cg(xld + (size_t)i * strideF);

            F8 o;
            #pragma unroll
            for (int e = 0; e < 4; ++e) {
                float x0 = xv.v[2*e], x1 = xv.v[2*e+1];
                float p0 = h.v[2*e],  p1 = h.v[2*e+1];
                float z0 = fmaf(a00, x0, fmaf(a01, x1, fmaf(w00, p0, fmaf(w01, p1, b0))));
                float z1 = fmaf(a10, x0, fmaf(a11, x1, fmaf(w10, p0, fmaf(w11, p1, b1))));
                float n0 = exact_tanh(z0);
                float n1 = exact_tanh(z1);
                h.v[2*e]   = n0;
                h.v[2*e+1] = n1;
                o.v[2*e]   = sig10(n0);
                o.v[2*e+1] = sig10(n1);
            }
            st256cs(ost + (size_t)i * strideF, o);
        }
        xld += (size_t)PF * strideF;
        ost += (size_t)PF * strideF;
    }

    // Cleanup groups: predicated loads.
    for (; t + PF <= T; t += PF) {
        #pragma unroll
        for (int i = 0; i < PF; ++i) {
            F8 xv = buf[i];
            if (t + i + PF < T) buf[i] = ld256cg(xld + (size_t)i * strideF);

            F8 o;
            #pragma unroll
            for (int e = 0; e < 4; ++e) {
                float x0 = xv.v[2*e], x1 = xv.v[2*e+1];
                float p0 = h.v[2*e],  p1 = h.v[2*e+1];
                float z0 = fmaf(a00, x0, fmaf(a01, x1, fmaf(w00, p0, fmaf(w01, p1, b0))));
                float z1 = fmaf(a10, x0, fmaf(a11, x1, fmaf(w10, p0, fmaf(w11, p1, b1))));
                float n0 = exact_tanh(z0);
                float n1 = exact_tanh(z1);
                h.v[2*e]   = n0;
                h.v[2*e+1] = n1;
                o.v[2*e]   = sig10(n0);
                o.v[2*e+1] = sig10(n1);
            }
            st256cs(ost + (size_t)i * strideF, o);
        }
        xld += (size_t)PF * strideF;
        ost += (size_t)PF * strideF;
    }

    // Scalar tail (T % PF != 0).
    for (int i = 0; t < T; ++t, ++i) {
        F8 xv = buf[i];
        F8 o;
        #pragma unroll
        for (int e = 0; e < 4; ++e) {
            float x0 = xv.v[2*e], x1 = xv.v[2*e+1];
            float p0 = h.v[2*e],  p1 = h.v[2*e+1];
            float z0 = fmaf(a00, x0, fmaf(a01, x1, fmaf(w00, p0, fmaf(w01, p1, b0))));
            float z1 = fmaf(a10, x0, fmaf(a11, x1, fmaf(w10, p0, fmaf(w11, p1, b1))));
            float n0 = exact_tanh(z0);
            float n1 = exact_tanh(z1);
            h.v[2*e]   = n0;
            h.v[2*e+1] = n1;
            o.v[2*e]   = sig10(n0);
            o.v[2*e+1] = sig10(n1);
        }
        st256cs(ost + (size_t)i * strideF, o);
    }

    st256cs(houtg + (size_t)q * 8, h);
}

// Fallback: R14 float4 kernel (for npairs odd).
__global__ void __launch_bounds__(256, 5)
rnn_f4_kernel(const float4* __restrict__ x4,
              const float4* __restrict__ h04,
              const float*  __restrict__ Wih,
              const float*  __restrict__ Whh,
              const float*  __restrict__ bih,
              const float*  __restrict__ bhh,
              float4* __restrict__ out4,
              float4* __restrict__ hout4,
              int T, int npairs)
{
    int p = blockIdx.x * blockDim.x + threadIdx.x;
    if (p >= npairs) return;

    const float a00 = Wih[0], a01 = Wih[1], a10 = Wih[2], a11 = Wih[3];
    const float w00 = Whh[0], w01 = Whh[1], w10 = Whh[2], w11 = Whh[3];
    const float b0 = bih[0] + bhh[0];
    const float b1 = bih[1] + bhh[1];

    float4 hv = h04[p];
    float hA0 = hv.x, hA1 = hv.y, hB0 = hv.z, hB1 = hv.w;

    float4 buf[PF];
    #pragma unroll
    for (int i = 0; i < PF; ++i) {
        int ti = (i < T) ? i : (T - 1);
        buf[i] = __ldcg(&x4[(size_t)ti * npairs + p]);
    }
    const float4* xld = x4 + (size_t)PF * npairs + p;
    float4*       ost = out4 + p;
    const size_t  stride = (size_t)npairs;

    for (int t = 0; t < T; ++t) {
        int i = t % PF;
        float4 xv = buf[i];
        if (t + PF < T) buf[i] = __ldcg(&xld[0]);
        xld += stride;

        float zA0 = fmaf(a00, xv.x, fmaf(a01, xv.y, fmaf(w00, hA0, fmaf(w01, hA1, b0))));
        float zA1 = fmaf(a10, xv.x, fmaf(a11, xv.y, fmaf(w10, hA0, fmaf(w11, hA1, b1))));
        float zB0 = fmaf(a00, xv.z, fmaf(a01, xv.w, fmaf(w00, hB0, fmaf(w01, hB1, b0))));
        float zB1 = fmaf(a10, xv.z, fmaf(a11, xv.w, fmaf(w10, hB0, fmaf(w11, hB1, b1))));
        hA0 = exact_tanh(zA0); hA1 = exact_tanh(zA1);
        hB0 = exact_tanh(zB0); hB1 = exact_tanh(zB1);
        float4 o;
        o.x = sig10(hA0); o.y = sig10(hA1); o.z = sig10(hB0); o.w = sig10(hB1);
        __stcs(ost, o);
        ost += stride;
    }

    float4 hf; hf.x = hA0; hf.y = hA1; hf.z = hB0; hf.w = hB1;
    hout4[p] = hf;
}

extern "C" void kernel_launch(void* const* d_in, const int* in_sizes, int n_in,
                              void* d_out, int out_size)
{
    const float* x   = (const float*)d_in[0];   // (T, B, 2)
    const float* h0  = (const float*)d_in[1];   // (1, B, 2)
    const float* Wih = (const float*)d_in[2];   // (2, 2)
    const float* Whh = (const float*)d_in[3];   // (2, 2)
    const float* bih = (const float*)d_in[4];   // (2,)
    const float* bhh = (const float*)d_in[5];   // (2,)

    const int BH = in_sizes[1];                 // B * H = B * 2
    const int B  = BH / 2;
    const int T  = in_sizes[0] / BH;

    float* out  = (float*)d_out;
    float* hout = out + ((size_t)out_size - (size_t)BH);

    if (B % 4 == 0) {
        const int nq = B / 4;                   // 4 batch elements per thread
        const int blocks = (nq + TPB - 1) / TPB;
        rnn_wide_kernel<<<blocks, TPB>>>(
            x, h0, Wih, Whh, bih, bhh, out, hout, T, nq);
    } else {
        const int npairs = B / 2;
        const int blocks = (npairs + 255) / 256;
        rnn_f4_kernel<<<blocks, 256>>>(
            (const float4*)x, (const float4*)h0,
            Wih, Whh, bih, bhh,
            (float4*)out, (float4*)hout, T, npairs);
    }
}

// round 16
// speedup vs baseline: 1.0240x; 1.0240x over previous
#include <cuda_runtime.h>
#include <cstddef>

// Pixel_RNNcontrol: h_t = tanh(x_t @ W_ih^T + h_{t-1} @ W_hh^T + b), out = sigmoid(10 h_t)
// T=128, B=262144, I=H=2. One thread handles 2 batch elements (float4 lanes).
//
// R16: R14 (best: 88.2us wall / 83.8 ncu / DRAM 75.3%) with ONE change:
// TPB 256 -> 224 (7 warps). 512 CTAs over 148 SMs = 3.46/SM (68 SMs carry 4,
// 80 carry 3 -> 15% straggler tail); 586 CTAs of 224 thr = 3.96/SM, near-
// uniform 28 warps/SM, cutting peak-SM work 12.5%. Same float4 width, PF=3,
// .cg loads, .cs stores, identical per-thread code.

#define PF  3   // prefetch depth
#define TPB 224

__device__ __forceinline__ float exact_tanh(float z) {
    // tanh(z) = 1 - 2/(1 + e^{2z}); z bounded (|z| <~ 7) -> no overflow
    float k = 2.885390082f * z;        // 2*log2(e) * z
    float e;
    asm("ex2.approx.f32 %0, %1;" : "=f"(e) : "f"(k));
    float r;
    float d = e + 1.0f;
    asm("rcp.approx.f32 %0, %1;" : "=f"(r) : "f"(d));
    return fmaf(-2.0f, r, 1.0f);
}

__device__ __forceinline__ float sig10(float h) {
    // sigmoid(10h) = 0.5 + 0.5*tanh(5h); HW tanh -> 1 MUFU, error non-accumulating
    float t;
    float a = 5.0f * h;
    asm("tanh.approx.f32 %0, %1;" : "=f"(t) : "f"(a));
    return fmaf(0.5f, t, 0.5f);
}

__global__ void __launch_bounds__(TPB, 5)
rnn_sigmoid_kernel(const float4* __restrict__ x4,
                   const float4* __restrict__ h04,
                   const float*  __restrict__ Wih,
                   const float*  __restrict__ Whh,
                   const float*  __restrict__ bih,
                   const float*  __restrict__ bhh,
                   float4* __restrict__ out4,
                   float4* __restrict__ hout4,
                   int T, int npairs)
{
    int p = blockIdx.x * TPB + threadIdx.x;
    if (p >= npairs) return;

    // 2x2 weights (row-major). z = x @ W^T  ->  z0 = W[0][0]*x0 + W[0][1]*x1
    const float a00 = Wih[0], a01 = Wih[1], a10 = Wih[2], a11 = Wih[3];
    const float w00 = Whh[0], w01 = Whh[1], w10 = Whh[2], w11 = Whh[3];
    const float b0 = bih[0] + bhh[0];
    const float b1 = bih[1] + bhh[1];

    float4 hv = h04[p];
    float hA0 = hv.x, hA1 = hv.y;   // batch element A
    float hB0 = hv.z, hB1 = hv.w;   // batch element B

    // Prime the pipeline: PF loads in flight before the loop.
    float4 buf[PF];
    #pragma unroll
    for (int i = 0; i < PF; ++i) {
        int ti = (i < T) ? i : (T - 1);
        buf[i] = __ldcg(&x4[(size_t)ti * npairs + p]);
    }

    const float4* xld = x4 + (size_t)PF * npairs + p;   // next load addr (t = PF)
    float4*       ost = out4 + p;                        // store addr (t = 0)
    const size_t  stride = (size_t)npairs;

    int t = 0;

    // Main loop: all PF prefetch loads guaranteed in-range (t + 2*PF <= T).
    for (; t + 2 * PF <= T; t += PF) {
        #pragma unroll
        for (int i = 0; i < PF; ++i) {
            float4 xv = buf[i];
            buf[i] = __ldcg(&xld[(size_t)i * stride]);   // unconditional, L2-only

            float zA0 = fmaf(a00, xv.x, fmaf(a01, xv.y, fmaf(w00, hA0, fmaf(w01, hA1, b0))));
            float zA1 = fmaf(a10, xv.x, fmaf(a11, xv.y, fmaf(w10, hA0, fmaf(w11, hA1, b1))));
            float zB0 = fmaf(a00, xv.z, fmaf(a01, xv.w, fmaf(w00, hB0, fmaf(w01, hB1, b0))));
            float zB1 = fmaf(a10, xv.z, fmaf(a11, xv.w, fmaf(w10, hB0, fmaf(w11, hB1, b1))));

            hA0 = exact_tanh(zA0);
            hA1 = exact_tanh(zA1);
            hB0 = exact_tanh(zB0);
            hB1 = exact_tanh(zB1);

            float4 o;
            o.x = sig10(hA0);
            o.y = sig10(hA1);
            o.z = sig10(hB0);
            o.w = sig10(hB1);
            __stcs(&ost[(size_t)i * stride], o);
        }
        xld += (size_t)PF * stride;
        ost += (size_t)PF * stride;
    }

    // Cleanup groups: predicated loads.
    for (; t + PF <= T; t += PF) {
        #pragma unroll
        for (int i = 0; i < PF; ++i) {
            float4 xv = buf[i];
            if (t + i + PF < T) buf[i] = __ldcg(&xld[(size_t)i * stride]);

            float zA0 = fmaf(a00, xv.x, fmaf(a01, xv.y, fmaf(w00, hA0, fmaf(w01, hA1, b0))));
            float zA1 = fmaf(a10, xv.x, fmaf(a11, xv.y, fmaf(w10, hA0, fmaf(w11, hA1, b1))));
            float zB0 = fmaf(a00, xv.z, fmaf(a01, xv.w, fmaf(w00, hB0, fmaf(w01, hB1, b0))));
            float zB1 = fmaf(a10, xv.z, fmaf(a11, xv.w, fmaf(w10, hB0, fmaf(w11, hB1, b1))));

            hA0 = exact_tanh(zA0);
            hA1 = exact_tanh(zA1);
            hB0 = exact_tanh(zB0);
            hB1 = exact_tanh(zB1);

            float4 o;
            o.x = sig10(hA0);
            o.y = sig10(hA1);
            o.z = sig10(hB0);
            o.w = sig10(hB1);
            __stcs(&ost[(size_t)i * stride], o);
        }
        xld += (size_t)PF * stride;
        ost += (size_t)PF * stride;
    }

    // Scalar tail (T % PF != 0).
    for (int i = 0; t < T; ++t, ++i) {
        float4 xv = buf[i];
        float zA0 = fmaf(a00, xv.x, fmaf(a01, xv.y, fmaf(w00, hA0, fmaf(w01, hA1, b0))));
        float zA1 = fmaf(a10, xv.x, fmaf(a11, xv.y, fmaf(w10, hA0, fmaf(w11, hA1, b1))));
        float zB0 = fmaf(a00, xv.z, fmaf(a01, xv.w, fmaf(w00, hB0, fmaf(w01, hB1, b0))));
        float zB1 = fmaf(a10, xv.z, fmaf(a11, xv.w, fmaf(w10, hB0, fmaf(w11, hB1, b1))));
        hA0 = exact_tanh(zA0);
        hA1 = exact_tanh(zA1);
        hB0 = exact_tanh(zB0);
        hB1 = exact_tanh(zB1);
        float4 o;
        o.x = sig10(hA0); o.y = sig10(hA1); o.z = sig10(hB0); o.w = sig10(hB1);
        __stcs(&ost[(size_t)i * stride], o);
    }

    float4 hf;
    hf.x = hA0; hf.y = hA1; hf.z = hB0; hf.w = hB1;
    hout4[p] = hf;
}

extern "C" void kernel_launch(void* const* d_in, const int* in_sizes, int n_in,
                              void* d_out, int out_size)
{
    const float* x   = (const float*)d_in[0];   // (T, B, 2)
    const float* h0  = (const float*)d_in[1];   // (1, B, 2)
    const float* Wih = (const float*)d_in[2];   // (2, 2)
    const float* Whh = (const float*)d_in[3];   // (2, 2)
    const float* bih = (const float*)d_in[4];   // (2,)
    const float* bhh = (const float*)d_in[5];   // (2,)

    const int BH = in_sizes[1];                 // B * H = B * 2
    const int B  = BH / 2;
    const int T  = in_sizes[0] / BH;            // (T*B*2) / (B*2)

    float* out = (float*)d_out;                 // first T*B*2 elems: out
    float* hout = out + ((size_t)out_size - (size_t)BH);  // last B*2 elems: hidden

    const int npairs = B / 2;                   // float4 granularity (2 batch elems)
    const int blocks = (npairs + TPB - 1) / TPB;

    rnn_sigmoid_kernel<<<blocks, TPB>>>(
        (const float4*)x, (const float4*)h0,
        Wih, Whh, bih, bhh,
        (float4*)out, (float4*)hout,
        T, npairs);
}